// round 1
// baseline (speedup 1.0000x reference)
#include <cuda_runtime.h>
#include <cuda_bf16.h>
#include <float.h>

#define Bn   4
#define Nn   8192
#define Cc   256
#define Kk   16
#define Ff   512
#define ROWS (Bn*Nn)

__device__ float4 g_pos4[ROWS];
__device__ float  g_M[Cc * Ff];
__device__ float  g_Y[(size_t)ROWS * Ff];
__device__ int    g_idx[ROWS * Kk];

__global__ void prep_pos_kernel(const float* __restrict__ qpos) {
    int i = blockIdx.x * blockDim.x + threadIdx.x;
    if (i >= ROWS) return;
    float x = qpos[i*3+0], y = qpos[i*3+1], z = qpos[i*3+2];
    float n = fmaf(z, z, fmaf(y, y, x * x));
    g_pos4[i] = make_float4(x, y, z, n);
}

__global__ void prep_M_kernel(const float* __restrict__ W) {
    int i = blockIdx.x * blockDim.x + threadIdx.x;
    if (i >= Cc * Ff) return;
    int r = i / Ff;
    int c = i % Ff;
    float v;
    if (c < Cc) v = W[r * Cc + c];
    else        v = W[(Cc + r) * Cc + (c - Cc)] - W[r * Cc + (c - Cc)];
    g_M[i] = v;
}

__global__ __launch_bounds__(128) void knn_kernel() {
    const int b = blockIdx.y;
    const int q = blockIdx.x * 128 + threadIdx.x;
    const float4* __restrict__ pos = g_pos4 + b * Nn;

    float4 me = pos[q];
    const float qx = me.x, qy = me.y, qz = me.z;

    float dist[Kk];
    int   nid[Kk];
#pragma unroll
    for (int i = 0; i < Kk; ++i) { dist[i] = FLT_MAX; nid[i] = 0; }

    __shared__ float4 sc[1024];

    for (int t0 = 0; t0 < Nn; t0 += 1024) {
#pragma unroll
        for (int j = 0; j < 8; ++j)
            sc[threadIdx.x + j * 128] = pos[t0 + threadIdx.x + j * 128];
        __syncthreads();

        float thr = dist[Kk - 1];
#pragma unroll 4
        for (int j = 0; j < 1024; ++j) {
            float4 c = sc[j];
            float t  = fmaf(qz, c.z, fmaf(qy, c.y, qx * c.x));
            float d2 = fmaf(-2.0f, t, c.w);
            if (d2 < thr) {
                float cd = d2; int ci = t0 + j;
#pragma unroll
                for (int s = 0; s < Kk; ++s) {
                    bool  p  = cd < dist[s];
                    float od = dist[s]; int oi = nid[s];
                    dist[s] = p ? cd : od;  nid[s] = p ? ci : oi;
                    cd      = p ? od : cd;  ci     = p ? oi : ci;
                }
                thr = dist[Kk - 1];
            }
        }
        __syncthreads();
    }

    int base = (b * Nn + q) * Kk;
#pragma unroll
    for (int i = 0; i < Kk; ++i) g_idx[base + i] = nid[i];
}

__global__ __launch_bounds__(256, 2) void sgemm_kernel(const float* __restrict__ A) {
    __shared__ float As[16][128];
    __shared__ float Bs[16][128];

    const int tid  = threadIdx.x;
    const int bm0  = blockIdx.y * 128;
    const int bn0  = blockIdx.x * 128;

    const int arow = tid >> 2;
    const int acol = (tid & 3) * 4;
    const int brow = tid >> 5;
    const int bcol = (tid & 31) * 4;

    const int tx = tid & 15, ty = tid >> 4;
    const int c0 = tx * 4, c1 = 64 + tx * 4;
    const int r0 = ty * 4, r1 = 64 + ty * 4;

    float acc[8][8];
#pragma unroll
    for (int i = 0; i < 8; ++i)
#pragma unroll
        for (int j = 0; j < 8; ++j) acc[i][j] = 0.0f;

    for (int kt = 0; kt < Cc; kt += 16) {
        float4 a0 = *(const float4*)(A + (size_t)(bm0 + arow)      * Cc + kt + acol);
        float4 a1 = *(const float4*)(A + (size_t)(bm0 + arow + 64) * Cc + kt + acol);
        float4 b0 = *(const float4*)(g_M + (size_t)(kt + brow)     * Ff + bn0 + bcol);
        float4 b1 = *(const float4*)(g_M + (size_t)(kt + brow + 8) * Ff + bn0 + bcol);

        __syncthreads();
        As[acol + 0][arow] = a0.x; As[acol + 1][arow] = a0.y;
        As[acol + 2][arow] = a0.z; As[acol + 3][arow] = a0.w;
        As[acol + 0][arow + 64] = a1.x; As[acol + 1][arow + 64] = a1.y;
        As[acol + 2][arow + 64] = a1.z; As[acol + 3][arow + 64] = a1.w;
        *(float4*)&Bs[brow][bcol]     = b0;
        *(float4*)&Bs[brow + 8][bcol] = b1;
        __syncthreads();

#pragma unroll
        for (int kk = 0; kk < 16; ++kk) {
            float4 af0 = *(const float4*)&As[kk][r0];
            float4 af1 = *(const float4*)&As[kk][r1];
            float4 bf0 = *(const float4*)&Bs[kk][c0];
            float4 bf1 = *(const float4*)&Bs[kk][c1];
            float ar[8] = {af0.x, af0.y, af0.z, af0.w, af1.x, af1.y, af1.z, af1.w};
            float br[8] = {bf0.x, bf0.y, bf0.z, bf0.w, bf1.x, bf1.y, bf1.z, bf1.w};
#pragma unroll
            for (int i = 0; i < 8; ++i)
#pragma unroll
                for (int j = 0; j < 8; ++j)
                    acc[i][j] = fmaf(ar[i], br[j], acc[i][j]);
        }
    }

#pragma unroll
    for (int i = 0; i < 8; ++i) {
        int row = bm0 + ((i < 4) ? (r0 + i) : (r1 + i - 4));
        float4 v0 = make_float4(acc[i][0], acc[i][1], acc[i][2], acc[i][3]);
        float4 v1 = make_float4(acc[i][4], acc[i][5], acc[i][6], acc[i][7]);
        *(float4*)(g_Y + (size_t)row * Ff + bn0 + c0) = v0;
        *(float4*)(g_Y + (size_t)row * Ff + bn0 + c1) = v1;
    }
}

__global__ __launch_bounds__(256) void gather_max_kernel(const float* __restrict__ bias,
                                                         float* __restrict__ out) {
    const int row  = blockIdx.x * 8 + (threadIdx.x >> 5);
    const int lane = threadIdx.x & 31;
    const int b    = row >> 13;

    const int* ir = g_idx + row * Kk;
    int myn = ir[lane & (Kk - 1)];

    const float* Ybase = g_Y + (size_t)(b << 13) * Ff;

    float4 m0 = make_float4(-FLT_MAX, -FLT_MAX, -FLT_MAX, -FLT_MAX);
    float4 m1 = m0;

#pragma unroll
    for (int j = 0; j < Kk; ++j) {
        int nb = __shfl_sync(0xffffffffu, myn, j);
        const float4* Pr = (const float4*)(Ybase + (size_t)nb * Ff);
        float4 a = Pr[lane];
        float4 c = Pr[lane + 32];
        m0.x = fmaxf(m0.x, a.x); m0.y = fmaxf(m0.y, a.y);
        m0.z = fmaxf(m0.z, a.z); m0.w = fmaxf(m0.w, a.w);
        m1.x = fmaxf(m1.x, c.x); m1.y = fmaxf(m1.y, c.y);
        m1.z = fmaxf(m1.z, c.z); m1.w = fmaxf(m1.w, c.w);
    }

    const float4* Ur = (const float4*)(g_Y + (size_t)row * Ff + Cc);
    float4 u0 = Ur[lane], u1 = Ur[lane + 32];
    const float4* Br = (const float4*)bias;
    float4 bb0 = Br[lane], bb1 = Br[lane + 32];

    float4 v0, v1;
    v0.x = m0.x + u0.x + bb0.x; v0.y = m0.y + u0.y + bb0.y;
    v0.z = m0.z + u0.z + bb0.z; v0.w = m0.w + u0.w + bb0.w;
    v1.x = m1.x + u1.x + bb1.x; v1.y = m1.y + u1.y + bb1.y;
    v1.z = m1.z + u1.z + bb1.z; v1.w = m1.w + u1.w + bb1.w;

    v0.x = fmaxf(v0.x, 0.2f * v0.x); v0.y = fmaxf(v0.y, 0.2f * v0.y);
    v0.z = fmaxf(v0.z, 0.2f * v0.z); v0.w = fmaxf(v0.w, 0.2f * v0.w);
    v1.x = fmaxf(v1.x, 0.2f * v1.x); v1.y = fmaxf(v1.y, 0.2f * v1.y);
    v1.z = fmaxf(v1.z, 0.2f * v1.z); v1.w = fmaxf(v1.w, 0.2f * v1.w);

    float4* Or = (float4*)(out + (size_t)row * Cc);
    Or[lane]      = v0;
    Or[lane + 32] = v1;
}

extern "C" void kernel_launch(void* const* d_in, const int* in_sizes, int n_in,
                              void* d_out, int out_size) {
    const float* q    = (const float*)d_in[0];   // [4,8192,256]
    const float* qpos = (const float*)d_in[1];   // [4,8192,3]
    const float* W    = (const float*)d_in[2];   // [512,256]
    const float* bias = (const float*)d_in[3];   // [256]
    float* out = (float*)d_out;
    (void)in_sizes; (void)n_in; (void)out_size;

    prep_pos_kernel<<<(ROWS + 255) / 256, 256>>>(qpos);
    prep_M_kernel<<<(Cc * Ff + 255) / 256, 256>>>(W);
    knn_kernel<<<dim3(Nn / 128, Bn), 128>>>();
    sgemm_kernel<<<dim3(Ff / 128, ROWS / 128), 256>>>(q);
    gather_max_kernel<<<ROWS / 8, 256>>>(bias, out);
}

// round 2
// speedup vs baseline: 1.0200x; 1.0200x over previous
#include <cuda_runtime.h>
#include <cuda_bf16.h>
#include <float.h>

#define Bn   4
#define Nn   8192
#define Cc   256
#define Kk   16
#define Ff   512
#define ROWS (Bn*Nn)

__device__ float4 g_pos4 [ROWS];   // original order: (x,y,z,|p|^2)
__device__ float4 g_pos4s[ROWS];   // sorted-by-x order
__device__ int    g_sid  [ROWS];   // sorted pos -> original idx (batch-local)
__device__ float  g_M[Cc * Ff];
__device__ float  g_Y[(size_t)ROWS * Ff];
__device__ int    g_idx[ROWS * Kk];

// ---------------------------------------------------------------------------
__global__ void prep_pos_kernel(const float* __restrict__ qpos) {
    int i = blockIdx.x * blockDim.x + threadIdx.x;
    if (i >= ROWS) return;
    float x = qpos[i*3+0], y = qpos[i*3+1], z = qpos[i*3+2];
    float n = fmaf(z, z, fmaf(y, y, x * x));
    g_pos4[i] = make_float4(x, y, z, n);
}

__global__ void prep_M_kernel(const float* __restrict__ W) {
    int i = blockIdx.x * blockDim.x + threadIdx.x;
    if (i >= Cc * Ff) return;
    int r = i / Ff;
    int c = i % Ff;
    float v;
    if (c < Cc) v = W[r * Cc + c];
    else        v = W[(Cc + r) * Cc + (c - Cc)] - W[r * Cc + (c - Cc)];
    g_M[i] = v;
}

// ---------------------------------------------------------------------------
// Heuristic spatial sort: per batch, bitonic-sort points by x.
// Key = sortable float bits of x, low 13 bits overwritten with the index
// (sort order approximate in x — purely a scan-order heuristic, KNN stays exact).
// ---------------------------------------------------------------------------
__global__ __launch_bounds__(512) void sort_kernel() {
    const int b   = blockIdx.x;
    const int tid = threadIdx.x;
    __shared__ unsigned sk[Nn];          // 32 KB

    for (int i = tid; i < Nn; i += 512) {
        unsigned u = __float_as_uint(g_pos4[b*Nn + i].x);
        u = (u & 0x80000000u) ? ~u : (u | 0x80000000u);   // monotone map
        sk[i] = (u & 0xFFFFE000u) | (unsigned)i;          // idx in low 13 bits
    }
    __syncthreads();

    for (int k = 2; k <= Nn; k <<= 1) {
        for (int j = k >> 1; j > 0; j >>= 1) {
            for (int t = tid; t < Nn/2; t += 512) {
                int i   = 2*t - (t & (j - 1));
                int ixj = i + j;
                unsigned a = sk[i], c = sk[ixj];
                bool asc = ((i & k) == 0);
                if ((a > c) == asc) { sk[i] = c; sk[ixj] = a; }
            }
            __syncthreads();
        }
    }

    for (int i = tid; i < Nn; i += 512) {
        int orig = (int)(sk[i] & 8191u);
        g_pos4s[b*Nn + i] = g_pos4[b*Nn + orig];
        g_sid  [b*Nn + i] = orig;
    }
}

// ---------------------------------------------------------------------------
// KNN over sorted points. One thread per (sorted) query.
// Tiles visited nearest-slab-first so the top-16 threshold tightens early.
// Insertion under a warp-uniform ballot branch (no divergent reconvergence).
// ---------------------------------------------------------------------------
__global__ __launch_bounds__(128) void knn_kernel() {
    const int b  = blockIdx.y;
    const int qs = blockIdx.x * 128 + threadIdx.x;     // sorted position
    const float4* __restrict__ pos = g_pos4s + b * Nn;
    const int*    __restrict__ sid = g_sid   + b * Nn;

    float4 me = pos[qs];
    const float qx = me.x, qy = me.y, qz = me.z;

    float dist[Kk];
    int   nid[Kk];
#pragma unroll
    for (int i = 0; i < Kk; ++i) { dist[i] = FLT_MAX; nid[i] = 0; }

    __shared__ float4 sc[1024];

    // tile visit order: own slab first, then outward
    const int ctile = blockIdx.x >> 3;                 // 1024 sorted pts per tile
    int order[8];
    {
        int n = 0;
        order[n++] = ctile;
        for (int d = 1; d < 8; ++d) {
            if (ctile + d < 8)  order[n++] = ctile + d;
            if (ctile - d >= 0) order[n++] = ctile - d;
        }
    }

    float thr = FLT_MAX;
    for (int ot = 0; ot < 8; ++ot) {
        const int t0 = order[ot] * 1024;
        __syncthreads();
#pragma unroll
        for (int j = 0; j < 8; ++j)
            sc[threadIdx.x + j * 128] = pos[t0 + threadIdx.x + j * 128];
        __syncthreads();

#pragma unroll 4
        for (int j = 0; j < 1024; ++j) {
            float4 c = sc[j];
            float t  = fmaf(qz, c.z, fmaf(qy, c.y, qx * c.x));
            float d2 = fmaf(-2.0f, t, c.w);
            bool p = d2 < thr;
            if (__ballot_sync(0xffffffffu, p)) {
                // sorted insert; lanes with !p swap nothing (d2 >= dist[15])
                float cd = d2; int ci = t0 + j;
#pragma unroll
                for (int s = 0; s < Kk; ++s) {
                    bool  sw = cd < dist[s];
                    float od = dist[s]; int oi = nid[s];
                    dist[s] = sw ? cd : od;  nid[s] = sw ? ci : oi;
                    cd      = sw ? od : cd;  ci     = sw ? oi : ci;
                }
                thr = dist[Kk - 1];
            }
        }
    }

    const int orig = sid[qs];
    const int base = (b * Nn + orig) * Kk;
#pragma unroll
    for (int i = 0; i < Kk; ++i) g_idx[base + i] = sid[nid[i]];
}

// ---------------------------------------------------------------------------
__global__ __launch_bounds__(256, 2) void sgemm_kernel(const float* __restrict__ A) {
    __shared__ float As[16][128];
    __shared__ float Bs[16][128];

    const int tid  = threadIdx.x;
    const int bm0  = blockIdx.y * 128;
    const int bn0  = blockIdx.x * 128;

    const int arow = tid >> 2;
    const int acol = (tid & 3) * 4;
    const int brow = tid >> 5;
    const int bcol = (tid & 31) * 4;

    const int tx = tid & 15, ty = tid >> 4;
    const int c0 = tx * 4, c1 = 64 + tx * 4;
    const int r0 = ty * 4, r1 = 64 + ty * 4;

    float acc[8][8];
#pragma unroll
    for (int i = 0; i < 8; ++i)
#pragma unroll
        for (int j = 0; j < 8; ++j) acc[i][j] = 0.0f;

    for (int kt = 0; kt < Cc; kt += 16) {
        float4 a0 = *(const float4*)(A + (size_t)(bm0 + arow)      * Cc + kt + acol);
        float4 a1 = *(const float4*)(A + (size_t)(bm0 + arow + 64) * Cc + kt + acol);
        float4 b0 = *(const float4*)(g_M + (size_t)(kt + brow)     * Ff + bn0 + bcol);
        float4 b1 = *(const float4*)(g_M + (size_t)(kt + brow + 8) * Ff + bn0 + bcol);

        __syncthreads();
        As[acol + 0][arow] = a0.x; As[acol + 1][arow] = a0.y;
        As[acol + 2][arow] = a0.z; As[acol + 3][arow] = a0.w;
        As[acol + 0][arow + 64] = a1.x; As[acol + 1][arow + 64] = a1.y;
        As[acol + 2][arow + 64] = a1.z; As[acol + 3][arow + 64] = a1.w;
        *(float4*)&Bs[brow][bcol]     = b0;
        *(float4*)&Bs[brow + 8][bcol] = b1;
        __syncthreads();

#pragma unroll
        for (int kk = 0; kk < 16; ++kk) {
            float4 af0 = *(const float4*)&As[kk][r0];
            float4 af1 = *(const float4*)&As[kk][r1];
            float4 bf0 = *(const float4*)&Bs[kk][c0];
            float4 bf1 = *(const float4*)&Bs[kk][c1];
            float ar[8] = {af0.x, af0.y, af0.z, af0.w, af1.x, af1.y, af1.z, af1.w};
            float br[8] = {bf0.x, bf0.y, bf0.z, bf0.w, bf1.x, bf1.y, bf1.z, bf1.w};
#pragma unroll
            for (int i = 0; i < 8; ++i)
#pragma unroll
                for (int j = 0; j < 8; ++j)
                    acc[i][j] = fmaf(ar[i], br[j], acc[i][j]);
        }
    }

#pragma unroll
    for (int i = 0; i < 8; ++i) {
        int row = bm0 + ((i < 4) ? (r0 + i) : (r1 + i - 4));
        float4 v0 = make_float4(acc[i][0], acc[i][1], acc[i][2], acc[i][3]);
        float4 v1 = make_float4(acc[i][4], acc[i][5], acc[i][6], acc[i][7]);
        *(float4*)(g_Y + (size_t)row * Ff + bn0 + c0) = v0;
        *(float4*)(g_Y + (size_t)row * Ff + bn0 + c1) = v1;
    }
}

// ---------------------------------------------------------------------------
__global__ __launch_bounds__(256) void gather_max_kernel(const float* __restrict__ bias,
                                                         float* __restrict__ out) {
    const int row  = blockIdx.x * 8 + (threadIdx.x >> 5);
    const int lane = threadIdx.x & 31;
    const int b    = row >> 13;

    const int* ir = g_idx + row * Kk;
    int myn = ir[lane & (Kk - 1)];

    const float* Ybase = g_Y + (size_t)(b << 13) * Ff;

    float4 m0 = make_float4(-FLT_MAX, -FLT_MAX, -FLT_MAX, -FLT_MAX);
    float4 m1 = m0;

#pragma unroll
    for (int j = 0; j < Kk; ++j) {
        int nb = __shfl_sync(0xffffffffu, myn, j);
        const float4* Pr = (const float4*)(Ybase + (size_t)nb * Ff);
        float4 a = Pr[lane];
        float4 c = Pr[lane + 32];
        m0.x = fmaxf(m0.x, a.x); m0.y = fmaxf(m0.y, a.y);
        m0.z = fmaxf(m0.z, a.z); m0.w = fmaxf(m0.w, a.w);
        m1.x = fmaxf(m1.x, c.x); m1.y = fmaxf(m1.y, c.y);
        m1.z = fmaxf(m1.z, c.z); m1.w = fmaxf(m1.w, c.w);
    }

    const float4* Ur = (const float4*)(g_Y + (size_t)row * Ff + Cc);
    float4 u0 = Ur[lane], u1 = Ur[lane + 32];
    const float4* Br = (const float4*)bias;
    float4 bb0 = Br[lane], bb1 = Br[lane + 32];

    float4 v0, v1;
    v0.x = m0.x + u0.x + bb0.x; v0.y = m0.y + u0.y + bb0.y;
    v0.z = m0.z + u0.z + bb0.z; v0.w = m0.w + u0.w + bb0.w;
    v1.x = m1.x + u1.x + bb1.x; v1.y = m1.y + u1.y + bb1.y;
    v1.z = m1.z + u1.z + bb1.z; v1.w = m1.w + u1.w + bb1.w;

    v0.x = fmaxf(v0.x, 0.2f * v0.x); v0.y = fmaxf(v0.y, 0.2f * v0.y);
    v0.z = fmaxf(v0.z, 0.2f * v0.z); v0.w = fmaxf(v0.w, 0.2f * v0.w);
    v1.x = fmaxf(v1.x, 0.2f * v1.x); v1.y = fmaxf(v1.y, 0.2f * v1.y);
    v1.z = fmaxf(v1.z, 0.2f * v1.z); v1.w = fmaxf(v1.w, 0.2f * v1.w);

    float4* Or = (float4*)(out + (size_t)row * Cc);
    Or[lane]      = v0;
    Or[lane + 32] = v1;
}

// ---------------------------------------------------------------------------
extern "C" void kernel_launch(void* const* d_in, const int* in_sizes, int n_in,
                              void* d_out, int out_size) {
    const float* q    = (const float*)d_in[0];   // [4,8192,256]
    const float* qpos = (const float*)d_in[1];   // [4,8192,3]
    const float* W    = (const float*)d_in[2];   // [512,256]
    const float* bias = (const float*)d_in[3];   // [256]
    float* out = (float*)d_out;
    (void)in_sizes; (void)n_in; (void)out_size;

    prep_pos_kernel<<<(ROWS + 255) / 256, 256>>>(qpos);
    sort_kernel<<<Bn, 512>>>();
    prep_M_kernel<<<(Cc * Ff + 255) / 256, 256>>>(W);
    knn_kernel<<<dim3(Nn / 128, Bn), 128>>>();
    sgemm_kernel<<<dim3(Ff / 128, ROWS / 128), 256>>>(q);
    gather_max_kernel<<<ROWS / 8, 256>>>(bias, out);
}